// round 3
// baseline (speedup 1.0000x reference)
#include <cuda_runtime.h>
#include <math.h>

#define NN 100000
#define NE 1600000
#define HD 128
#define EPSV 1e-5f

// ---------------- scratch (static device globals; no allocation) ----------------
__device__ int   g_deg[NN];
__device__ int   g_fill[NN];
__device__ int   g_off[NN + 1];
__device__ float g_dinv[NN];
__device__ int   g_csrc[NE];
__device__ float g_bufA[(size_t)NN * HD];
__device__ float g_bufB[(size_t)NN * HD];
__device__ float g_Wc[HD * 2];
__device__ float g_bc[2];

// ---------------- graph preprocessing ----------------
__global__ void k_zero() {
    int i = blockIdx.x * blockDim.x + threadIdx.x;
    if (i < NN) { g_deg[i] = 0; g_fill[i] = 0; }
}

__global__ void k_count(const int* __restrict__ dst) {
    int i = blockIdx.x * blockDim.x + threadIdx.x;
    if (i < NE) atomicAdd(&g_deg[dst[i]], 1);
}

// single-block exclusive scan of g_deg -> g_off ; also dinv = rsqrt(deg+1)
__global__ void k_scan() {
    __shared__ int ss[1024];
    const int T = 1024;
    const int CH = (NN + T - 1) / T;
    int t = threadIdx.x;
    int lo = t * CH; if (lo > NN) lo = NN;
    int hi = lo + CH; if (hi > NN) hi = NN;
    int s = 0;
    for (int i = lo; i < hi; i++) s += g_deg[i];
    ss[t] = s;
    __syncthreads();
    for (int d = 1; d < T; d <<= 1) {
        int v = (t >= d) ? ss[t - d] : 0;
        __syncthreads();
        ss[t] += v;
        __syncthreads();
    }
    int run = (t == 0) ? 0 : ss[t - 1];
    for (int i = lo; i < hi; i++) {
        g_off[i] = run;
        int dg = g_deg[i];
        run += dg;
        g_dinv[i] = rsqrtf((float)(dg + 1));   // +1 self loop
    }
    if (t == T - 1) g_off[NN] = run;
}

__global__ void k_scatter(const int* __restrict__ src, const int* __restrict__ dst) {
    int i = blockIdx.x * blockDim.x + threadIdx.x;
    if (i < NE) {
        int d = dst[i];
        int p = g_off[d] + atomicAdd(&g_fill[d], 1);
        g_csrc[p] = src[i];
    }
}

// ---------------- SGEMM: C[M,128] = A[M,128] @ B[128,128] ----------------
__global__ void sgemm128(const float* __restrict__ A, const float* __restrict__ B,
                         float* __restrict__ C) {
    __shared__ float As[64][16];   // [m][k]
    __shared__ float Bs[16][64];   // [k][n]
    int tid = threadIdx.x;         // 256
    int bm = blockIdx.x * 64;
    int bn = blockIdx.y * 64;
    int ty = tid >> 4, tx = tid & 15;
    float acc[4][4] = {};
    for (int kt = 0; kt < 128; kt += 16) {
        // load A tile (64x16): thread loads float4
        int row = tid >> 2, kc = (tid & 3) * 4;
        int gr = bm + row;
        float4 av = (gr < NN) ? *(const float4*)(A + (size_t)gr * 128 + kt + kc)
                              : make_float4(0.f, 0.f, 0.f, 0.f);
        *(float4*)&As[row][kc] = av;
        // load B tile (16x64)
        int bk = tid >> 4, nn = (tid & 15) * 4;
        float4 bv = *(const float4*)(B + (size_t)(kt + bk) * 128 + bn + nn);
        *(float4*)&Bs[bk][nn] = bv;
        __syncthreads();
#pragma unroll
        for (int kk = 0; kk < 16; kk++) {
            float a0 = As[ty * 4 + 0][kk];
            float a1 = As[ty * 4 + 1][kk];
            float a2 = As[ty * 4 + 2][kk];
            float a3 = As[ty * 4 + 3][kk];
            float4 bq = *(const float4*)&Bs[kk][tx * 4];
            acc[0][0] += a0 * bq.x; acc[0][1] += a0 * bq.y; acc[0][2] += a0 * bq.z; acc[0][3] += a0 * bq.w;
            acc[1][0] += a1 * bq.x; acc[1][1] += a1 * bq.y; acc[1][2] += a1 * bq.z; acc[1][3] += a1 * bq.w;
            acc[2][0] += a2 * bq.x; acc[2][1] += a2 * bq.y; acc[2][2] += a2 * bq.z; acc[2][3] += a2 * bq.w;
            acc[3][0] += a3 * bq.x; acc[3][1] += a3 * bq.y; acc[3][2] += a3 * bq.z; acc[3][3] += a3 * bq.w;
        }
        __syncthreads();
    }
#pragma unroll
    for (int i = 0; i < 4; i++) {
        int gr = bm + ty * 4 + i;
        if (gr < NN) {
            float4 v = make_float4(acc[i][0], acc[i][1], acc[i][2], acc[i][3]);
            *(float4*)(C + (size_t)gr * 128 + bn + tx * 4) = v;
        }
    }
}

// ---------------- aggregation (+bias [+relu+LN]) ; warp per node ----------------
__global__ void k_agg(const float* __restrict__ lin, const float* __restrict__ bias,
                      const float* __restrict__ lng, const float* __restrict__ lnb,
                      float* __restrict__ outp, int doLN) {
    int gtid = blockIdx.x * blockDim.x + threadIdx.x;
    int node = gtid >> 5;
    if (node >= NN) return;
    int lane = gtid & 31;

    float dn = g_dinv[node];
    const float4* rowp = (const float4*)(lin + (size_t)node * HD);
    float4 v = rowp[lane];
    float w0 = dn * dn;                       // self loop
    float4 acc = make_float4(v.x * w0, v.y * w0, v.z * w0, v.w * w0);

    int e0 = g_off[node], e1 = g_off[node + 1];
    int e = e0;
    // unrolled x8: batch index loads, then 8 independent float4 gathers (MLP=8)
    for (; e + 8 <= e1; e += 8) {
        int s0 = g_csrc[e + 0];
        int s1 = g_csrc[e + 1];
        int s2 = g_csrc[e + 2];
        int s3 = g_csrc[e + 3];
        int s4 = g_csrc[e + 4];
        int s5 = g_csrc[e + 5];
        int s6 = g_csrc[e + 6];
        int s7 = g_csrc[e + 7];
        float w_0 = g_dinv[s0] * dn;
        float w_1 = g_dinv[s1] * dn;
        float w_2 = g_dinv[s2] * dn;
        float w_3 = g_dinv[s3] * dn;
        float w_4 = g_dinv[s4] * dn;
        float w_5 = g_dinv[s5] * dn;
        float w_6 = g_dinv[s6] * dn;
        float w_7 = g_dinv[s7] * dn;
        float4 u0 = ((const float4*)(lin + (size_t)s0 * HD))[lane];
        float4 u1 = ((const float4*)(lin + (size_t)s1 * HD))[lane];
        float4 u2 = ((const float4*)(lin + (size_t)s2 * HD))[lane];
        float4 u3 = ((const float4*)(lin + (size_t)s3 * HD))[lane];
        float4 u4 = ((const float4*)(lin + (size_t)s4 * HD))[lane];
        float4 u5 = ((const float4*)(lin + (size_t)s5 * HD))[lane];
        float4 u6 = ((const float4*)(lin + (size_t)s6 * HD))[lane];
        float4 u7 = ((const float4*)(lin + (size_t)s7 * HD))[lane];
        acc.x += u0.x * w_0; acc.y += u0.y * w_0; acc.z += u0.z * w_0; acc.w += u0.w * w_0;
        acc.x += u1.x * w_1; acc.y += u1.y * w_1; acc.z += u1.z * w_1; acc.w += u1.w * w_1;
        acc.x += u2.x * w_2; acc.y += u2.y * w_2; acc.z += u2.z * w_2; acc.w += u2.w * w_2;
        acc.x += u3.x * w_3; acc.y += u3.y * w_3; acc.z += u3.z * w_3; acc.w += u3.w * w_3;
        acc.x += u4.x * w_4; acc.y += u4.y * w_4; acc.z += u4.z * w_4; acc.w += u4.w * w_4;
        acc.x += u5.x * w_5; acc.y += u5.y * w_5; acc.z += u5.z * w_5; acc.w += u5.w * w_5;
        acc.x += u6.x * w_6; acc.y += u6.y * w_6; acc.z += u6.z * w_6; acc.w += u6.w * w_6;
        acc.x += u7.x * w_7; acc.y += u7.y * w_7; acc.z += u7.z * w_7; acc.w += u7.w * w_7;
    }
    for (; e < e1; e++) {
        int s = g_csrc[e];
        float w = g_dinv[s] * dn;
        float4 u = ((const float4*)(lin + (size_t)s * HD))[lane];
        acc.x += u.x * w; acc.y += u.y * w; acc.z += u.z * w; acc.w += u.w * w;
    }
    float4 bb = ((const float4*)bias)[lane];
    acc.x += bb.x; acc.y += bb.y; acc.z += bb.z; acc.w += bb.w;

    if (doLN) {
        // relu
        acc.x = fmaxf(acc.x, 0.f); acc.y = fmaxf(acc.y, 0.f);
        acc.z = fmaxf(acc.z, 0.f); acc.w = fmaxf(acc.w, 0.f);
        // layernorm over 128
        float s1 = acc.x + acc.y + acc.z + acc.w;
        float s2 = acc.x * acc.x + acc.y * acc.y + acc.z * acc.z + acc.w * acc.w;
#pragma unroll
        for (int o = 16; o > 0; o >>= 1) {
            s1 += __shfl_xor_sync(0xffffffffu, s1, o);
            s2 += __shfl_xor_sync(0xffffffffu, s2, o);
        }
        float mu = s1 * (1.0f / HD);
        float var = s2 * (1.0f / HD) - mu * mu;
        float r = rsqrtf(var + EPSV);
        float4 gg = ((const float4*)lng)[lane];
        float4 bl = ((const float4*)lnb)[lane];
        acc.x = (acc.x - mu) * r * gg.x + bl.x;
        acc.y = (acc.y - mu) * r * gg.y + bl.y;
        acc.z = (acc.z - mu) * r * gg.z + bl.z;
        acc.w = (acc.w - mu) * r * gg.w + bl.w;
    }
    ((float4*)(outp + (size_t)node * HD))[lane] = acc;
}

// ---------------- MLP head collapse: Wc = W1@W2 [128,2], bc = b1@W2 + b2 ----------------
__global__ void k_compose(const float* __restrict__ mpW1, const float* __restrict__ mpW2,
                          const float* __restrict__ mpb1, const float* __restrict__ mpb2) {
    int t = threadIdx.x;     // 256
    int k = t >> 1, c = t & 1;
    float s = 0.f;
    for (int j = 0; j < 128; j++) s += mpW1[k * 128 + j] * mpW2[j * 2 + c];
    g_Wc[k * 2 + c] = s;
    if (t < 2) {
        float sb = 0.f;
        for (int j = 0; j < 128; j++) sb += mpb1[j] * mpW2[j * 2 + t];
        g_bc[t] = sb + mpb2[t];
    }
}

// ---------------- head: relu(emb) @ Wc + bc, log_softmax ; warp per node ----------------
__global__ void k_head(const float* __restrict__ emb, float* __restrict__ logp) {
    int gtid = blockIdx.x * blockDim.x + threadIdx.x;
    int node = gtid >> 5;
    if (node >= NN) return;
    int lane = gtid & 31;

    float4 v = ((const float4*)(emb + (size_t)node * HD))[lane];
    v.x = fmaxf(v.x, 0.f); v.y = fmaxf(v.y, 0.f);
    v.z = fmaxf(v.z, 0.f); v.w = fmaxf(v.w, 0.f);
    // Wc layout [128][2]; lane covers k = 4*lane .. 4*lane+3
    const float4* wp = (const float4*)g_Wc;
    float4 wa = wp[lane * 2];       // (k0c0,k0c1,k1c0,k1c1)
    float4 wb = wp[lane * 2 + 1];   // (k2c0,k2c1,k3c0,k3c1)
    float l0 = v.x * wa.x + v.y * wa.z + v.z * wb.x + v.w * wb.z;
    float l1 = v.x * wa.y + v.y * wa.w + v.z * wb.y + v.w * wb.w;
#pragma unroll
    for (int o = 16; o > 0; o >>= 1) {
        l0 += __shfl_xor_sync(0xffffffffu, l0, o);
        l1 += __shfl_xor_sync(0xffffffffu, l1, o);
    }
    if (lane == 0) {
        l0 += g_bc[0]; l1 += g_bc[1];
        float m = fmaxf(l0, l1);
        float lse = m + logf(expf(l0 - m) + expf(l1 - m));
        logp[(size_t)node * 2 + 0] = l0 - lse;
        logp[(size_t)node * 2 + 1] = l1 - lse;
    }
}

// ---------------- launch ----------------
extern "C" void kernel_launch(void* const* d_in, const int* in_sizes, int n_in,
                              void* d_out, int out_size) {
    const float* x    = (const float*)d_in[0];
    const int*   ei   = (const int*)d_in[1];
    const int*   srcI = ei;
    const int*   dstI = ei + NE;
    const float* W1 = (const float*)d_in[2];
    const float* b1 = (const float*)d_in[3];
    const float* W2 = (const float*)d_in[4];
    const float* b2 = (const float*)d_in[5];
    const float* W3 = (const float*)d_in[6];
    const float* b3 = (const float*)d_in[7];
    const float* ln1g = (const float*)d_in[8];
    const float* ln1b = (const float*)d_in[9];
    const float* ln2g = (const float*)d_in[10];
    const float* ln2b = (const float*)d_in[11];
    const float* mpW1 = (const float*)d_in[12];
    const float* mpb1 = (const float*)d_in[13];
    const float* mpW2 = (const float*)d_in[14];
    const float* mpb2 = (const float*)d_in[15];

    float* out  = (float*)d_out;
    float* emb  = out;                      // [NN,128]
    float* logp = out + (size_t)NN * HD;    // [NN,2]

    float *bufA, *bufB;
    cudaGetSymbolAddress((void**)&bufA, g_bufA);
    cudaGetSymbolAddress((void**)&bufB, g_bufB);

    // graph preprocessing (per launch; deterministic up to fp tolerance)
    k_zero<<<(NN + 255) / 256, 256>>>();
    k_count<<<(NE + 255) / 256, 256>>>(dstI);
    k_scan<<<1, 1024>>>();
    k_scatter<<<(NE + 255) / 256, 256>>>(srcI, dstI);

    dim3 gg((NN + 63) / 64, 2);
    int aggBlocks = (NN * 32 + 255) / 256;

    // layer 0
    sgemm128<<<gg, 256>>>(x, W1, bufA);
    k_agg<<<aggBlocks, 256>>>(bufA, b1, ln1g, ln1b, bufB, 1);
    // layer 1
    sgemm128<<<gg, 256>>>(bufB, W2, bufA);
    k_agg<<<aggBlocks, 256>>>(bufA, b2, ln2g, ln2b, bufB, 1);
    // layer 2 -> emb
    sgemm128<<<gg, 256>>>(bufB, W3, bufA);
    k_agg<<<aggBlocks, 256>>>(bufA, b3, nullptr, nullptr, emb, 0);
    // head
    k_compose<<<1, 256>>>(mpW1, mpW2, mpb1, mpb2);
    k_head<<<aggBlocks, 256>>>(emb, logp);
}